// round 16
// baseline (speedup 1.0000x reference)
#include <cuda_runtime.h>
#include <cstddef>

#define BATCH 8192
#define F_DIM 1024
#define PF_DIM 1024
#define LOW 128
#define MID 32
#define PARAMS_DIM (2 * LOW * MID)   // 8192

// Scratch (allocation-free rule: __device__ globals)
__device__ float d_f_low[BATCH * LOW];
__device__ float d_pf_low[BATCH * LOW];
__device__ float d_params[(size_t)BATCH * PARAMS_DIM];   // 268 MB
__device__ float d_g[BATCH * LOW];

#define BM 128
#define BN 128
#define BK 16

// C[M,N] = A[M,K] @ B[N,K]^T + bias[N] (+ add1 + add2 elementwise), all fp32.
__global__ __launch_bounds__(256, 2) void sgemm_bias_kernel(
    const float* __restrict__ A, const float* __restrict__ B,
    const float* __restrict__ bias, float* __restrict__ C,
    int M, int N, int K,
    const float* __restrict__ add1, const float* __restrict__ add2)
{
    __shared__ float As[BK][BM];
    __shared__ float Bs[BK][BN];

    const int tid = threadIdx.x;
    const int bm = blockIdx.y * BM;
    const int bn = blockIdx.x * BN;

    // tile-load indexing: 256 threads, float4 loads, 2 row passes
    const int lr = tid >> 2;          // 0..63
    const int lc = (tid & 3) << 2;    // 0,4,8,12

    // 16x16 thread grid, 8x8 microtile
    const int tr = (tid >> 4) << 3;
    const int tc = (tid & 15) << 3;

    float acc[8][8] = {};

    for (int k0 = 0; k0 < K; k0 += BK) {
#pragma unroll
        for (int p = 0; p < 2; p++) {
            int r = lr + p * 64;
            float4 va = *(const float4*)(A + (size_t)(bm + r) * K + k0 + lc);
            As[lc + 0][r] = va.x; As[lc + 1][r] = va.y;
            As[lc + 2][r] = va.z; As[lc + 3][r] = va.w;
            float4 vb = *(const float4*)(B + (size_t)(bn + r) * K + k0 + lc);
            Bs[lc + 0][r] = vb.x; Bs[lc + 1][r] = vb.y;
            Bs[lc + 2][r] = vb.z; Bs[lc + 3][r] = vb.w;
        }
        __syncthreads();

#pragma unroll
        for (int kk = 0; kk < BK; kk++) {
            float ra[8], rb[8];
#pragma unroll
            for (int i = 0; i < 8; i++) ra[i] = As[kk][tr + i];
#pragma unroll
            for (int j = 0; j < 8; j++) rb[j] = Bs[kk][tc + j];
#pragma unroll
            for (int i = 0; i < 8; i++)
#pragma unroll
                for (int j = 0; j < 8; j++)
                    acc[i][j] = fmaf(ra[i], rb[j], acc[i][j]);
        }
        __syncthreads();
    }

#pragma unroll
    for (int i = 0; i < 8; i++) {
        size_t row = (size_t)(bm + tr + i);
#pragma unroll
        for (int j = 0; j < 8; j++) {
            size_t idx = row * (size_t)N + (size_t)(bn + tc + j);
            float v = acc[i][j] + bias[bn + tc + j];
            if (add1) v += add1[idx];
            if (add2) v += add2[idx];
            C[idx] = v;
        }
    }
}

// Per-sample tiny MLP: h = relu(f_low . p1), g = h . p2. One warp per sample.
// params[b, l*32+m] = p1[b,l,m]; params[b, 4096 + m*128 + l] = p2[b,m,l].
__global__ __launch_bounds__(256) void tiny_mlp_kernel(
    const float* __restrict__ f_low,
    const float* __restrict__ params,
    float* __restrict__ g_out)
{
    int warp = (blockIdx.x * blockDim.x + threadIdx.x) >> 5;
    int lane = threadIdx.x & 31;
    if (warp >= BATCH) return;

    const float* pr = params + (size_t)warp * PARAMS_DIM;
    const float* fl = f_low + (size_t)warp * LOW;

    // h[lane] = sum_l fl[l] * p1[l, lane]   (lane == m; coalesced reads)
    float h = 0.f;
#pragma unroll 8
    for (int l = 0; l < LOW; l++) {
        h = fmaf(__ldg(&fl[l]), pr[l * MID + lane], h);
    }
    h = fmaxf(h, 0.f);

    // g[l] = sum_m h[m] * p2[m, l]; lane covers l = lane + 32*j
    const float* p2 = pr + LOW * MID;
    float g0 = 0.f, g1 = 0.f, g2 = 0.f, g3 = 0.f;
#pragma unroll
    for (int m = 0; m < MID; m++) {
        float hm = __shfl_sync(0xffffffffu, h, m);
        g0 = fmaf(hm, p2[m * LOW + lane +  0], g0);
        g1 = fmaf(hm, p2[m * LOW + lane + 32], g1);
        g2 = fmaf(hm, p2[m * LOW + lane + 64], g2);
        g3 = fmaf(hm, p2[m * LOW + lane + 96], g3);
    }
    float* go = g_out + (size_t)warp * LOW;
    go[lane +  0] = g0;
    go[lane + 32] = g1;
    go[lane + 64] = g2;
    go[lane + 96] = g3;
}

extern "C" void kernel_launch(void* const* d_in, const int* in_sizes, int n_in,
                              void* d_out, int out_size)
{
    const float* f   = (const float*)d_in[0];
    const float* pf  = (const float*)d_in[1];
    const float* wf  = (const float*)d_in[2];   // (LOW, F_DIM)
    const float* bf  = (const float*)d_in[3];
    const float* wpf = (const float*)d_in[4];   // (LOW, PF_DIM)
    const float* bpf = (const float*)d_in[5];
    const float* wf2 = (const float*)d_in[6];   // (F_DIM, LOW)
    const float* bf2 = (const float*)d_in[7];
    const float* pgw = (const float*)d_in[8];   // (PARAMS_DIM, LOW)
    const float* pgb = (const float*)d_in[9];
    float* out = (float*)d_out;

    float *f_low, *pf_low, *params, *g;
    cudaGetSymbolAddress((void**)&f_low, d_f_low);
    cudaGetSymbolAddress((void**)&pf_low, d_pf_low);
    cudaGetSymbolAddress((void**)&params, d_params);
    cudaGetSymbolAddress((void**)&g, d_g);

    dim3 blk(256);

    // f_low = f @ wf^T + bf         (8192 x 128, K=1024)
    sgemm_bias_kernel<<<dim3(LOW / BN, BATCH / BM), blk>>>(
        f, wf, bf, f_low, BATCH, LOW, F_DIM, nullptr, nullptr);

    // pf_low = pf @ wpf^T + bpf
    sgemm_bias_kernel<<<dim3(LOW / BN, BATCH / BM), blk>>>(
        pf, wpf, bpf, pf_low, BATCH, LOW, PF_DIM, nullptr, nullptr);

    // params = pf_low @ pgw^T + pgb (8192 x 8192, K=128) -- the big one
    sgemm_bias_kernel<<<dim3(PARAMS_DIM / BN, BATCH / BM), blk>>>(
        pf_low, pgw, pgb, params, BATCH, PARAMS_DIM, LOW, nullptr, nullptr);

    // per-sample tiny MLP -> g (8192 x 128)
    tiny_mlp_kernel<<<BATCH / 8, 256>>>(f_low, params, g);

    // out = g @ wf2^T + bf2 + f + pf (8192 x 1024, K=128)
    sgemm_bias_kernel<<<dim3(F_DIM / BN, BATCH / BM), blk>>>(
        g, wf2, bf2, out, BATCH, F_DIM, LOW, f, pf);
}

// round 17
// speedup vs baseline: 1.0009x; 1.0009x over previous
#include <cuda_runtime.h>
#include <cstddef>

#define BATCH 8192
#define F_DIM 1024
#define PF_DIM 1024
#define LOW 128
#define MID 32
#define PARAMS_DIM (2 * LOW * MID)   // 8192

// Scratch (allocation-free rule: __device__ globals)
__device__ float d_f_low[BATCH * LOW];
__device__ float d_pf_low[BATCH * LOW];
__device__ float d_params[(size_t)BATCH * PARAMS_DIM];   // 268 MB
__device__ float d_g[BATCH * LOW];

#define BM 128
#define BN 128
#define BK 16

// C[M,N] = A[M,K] @ B[N,K]^T + bias[N] (+ add1 + add2 elementwise), all fp32.
__global__ __launch_bounds__(256, 2) void sgemm_bias_kernel(
    const float* __restrict__ A, const float* __restrict__ B,
    const float* __restrict__ bias, float* __restrict__ C,
    int M, int N, int K,
    const float* __restrict__ add1, const float* __restrict__ add2)
{
    __shared__ float As[BK][BM];
    __shared__ float Bs[BK][BN];

    const int tid = threadIdx.x;
    const int bm = blockIdx.y * BM;
    const int bn = blockIdx.x * BN;

    // tile-load indexing: 256 threads, float4 loads, 2 row passes
    const int lr = tid >> 2;          // 0..63
    const int lc = (tid & 3) << 2;    // 0,4,8,12

    // 16x16 thread grid, 8x8 microtile
    const int tr = (tid >> 4) << 3;
    const int tc = (tid & 15) << 3;

    float acc[8][8] = {};

    for (int k0 = 0; k0 < K; k0 += BK) {
#pragma unroll
        for (int p = 0; p < 2; p++) {
            int r = lr + p * 64;
            float4 va = *(const float4*)(A + (size_t)(bm + r) * K + k0 + lc);
            As[lc + 0][r] = va.x; As[lc + 1][r] = va.y;
            As[lc + 2][r] = va.z; As[lc + 3][r] = va.w;
            float4 vb = *(const float4*)(B + (size_t)(bn + r) * K + k0 + lc);
            Bs[lc + 0][r] = vb.x; Bs[lc + 1][r] = vb.y;
            Bs[lc + 2][r] = vb.z; Bs[lc + 3][r] = vb.w;
        }
        __syncthreads();

#pragma unroll
        for (int kk = 0; kk < BK; kk++) {
            float ra[8], rb[8];
#pragma unroll
            for (int i = 0; i < 8; i++) ra[i] = As[kk][tr + i];
#pragma unroll
            for (int j = 0; j < 8; j++) rb[j] = Bs[kk][tc + j];
#pragma unroll
            for (int i = 0; i < 8; i++)
#pragma unroll
                for (int j = 0; j < 8; j++)
                    acc[i][j] = fmaf(ra[i], rb[j], acc[i][j]);
        }
        __syncthreads();
    }

#pragma unroll
    for (int i = 0; i < 8; i++) {
        size_t row = (size_t)(bm + tr + i);
#pragma unroll
        for (int j = 0; j < 8; j++) {
            size_t idx = row * (size_t)N + (size_t)(bn + tc + j);
            float v = acc[i][j] + bias[bn + tc + j];
            if (add1) v += add1[idx];
            if (add2) v += add2[idx];
            C[idx] = v;
        }
    }
}

// Per-sample tiny MLP: h = relu(f_low . p1), g = h . p2. One warp per sample.
// params[b, l*32+m] = p1[b,l,m]; params[b, 4096 + m*128 + l] = p2[b,m,l].
__global__ __launch_bounds__(256) void tiny_mlp_kernel(
    const float* __restrict__ f_low,
    const float* __restrict__ params,
    float* __restrict__ g_out)
{
    int warp = (blockIdx.x * blockDim.x + threadIdx.x) >> 5;
    int lane = threadIdx.x & 31;
    if (warp >= BATCH) return;

    const float* pr = params + (size_t)warp * PARAMS_DIM;
    const float* fl = f_low + (size_t)warp * LOW;

    // h[lane] = sum_l fl[l] * p1[l, lane]   (lane == m; coalesced reads)
    float h = 0.f;
#pragma unroll 8
    for (int l = 0; l < LOW; l++) {
        h = fmaf(__ldg(&fl[l]), pr[l * MID + lane], h);
    }
    h = fmaxf(h, 0.f);

    // g[l] = sum_m h[m] * p2[m, l]; lane covers l = lane + 32*j
    const float* p2 = pr + LOW * MID;
    float g0 = 0.f, g1 = 0.f, g2 = 0.f, g3 = 0.f;
#pragma unroll
    for (int m = 0; m < MID; m++) {
        float hm = __shfl_sync(0xffffffffu, h, m);
        g0 = fmaf(hm, p2[m * LOW + lane +  0], g0);
        g1 = fmaf(hm, p2[m * LOW + lane + 32], g1);
        g2 = fmaf(hm, p2[m * LOW + lane + 64], g2);
        g3 = fmaf(hm, p2[m * LOW + lane + 96], g3);
    }
    float* go = g_out + (size_t)warp * LOW;
    go[lane +  0] = g0;
    go[lane + 32] = g1;
    go[lane + 64] = g2;
    go[lane + 96] = g3;
}

extern "C" void kernel_launch(void* const* d_in, const int* in_sizes, int n_in,
                              void* d_out, int out_size)
{
    const float* f   = (const float*)d_in[0];
    const float* pf  = (const float*)d_in[1];
    const float* wf  = (const float*)d_in[2];   // (LOW, F_DIM)
    const float* bf  = (const float*)d_in[3];
    const float* wpf = (const float*)d_in[4];   // (LOW, PF_DIM)
    const float* bpf = (const float*)d_in[5];
    const float* wf2 = (const float*)d_in[6];   // (F_DIM, LOW)
    const float* bf2 = (const float*)d_in[7];
    const float* pgw = (const float*)d_in[8];   // (PARAMS_DIM, LOW)
    const float* pgb = (const float*)d_in[9];
    float* out = (float*)d_out;

    float *f_low, *pf_low, *params, *g;
    cudaGetSymbolAddress((void**)&f_low, d_f_low);
    cudaGetSymbolAddress((void**)&pf_low, d_pf_low);
    cudaGetSymbolAddress((void**)&params, d_params);
    cudaGetSymbolAddress((void**)&g, d_g);

    dim3 blk(256);

    // f_low = f @ wf^T + bf         (8192 x 128, K=1024)
    sgemm_bias_kernel<<<dim3(LOW / BN, BATCH / BM), blk>>>(
        f, wf, bf, f_low, BATCH, LOW, F_DIM, nullptr, nullptr);

    // pf_low = pf @ wpf^T + bpf
    sgemm_bias_kernel<<<dim3(LOW / BN, BATCH / BM), blk>>>(
        pf, wpf, bpf, pf_low, BATCH, LOW, PF_DIM, nullptr, nullptr);

    // params = pf_low @ pgw^T + pgb (8192 x 8192, K=128) -- the big one
    sgemm_bias_kernel<<<dim3(PARAMS_DIM / BN, BATCH / BM), blk>>>(
        pf_low, pgw, pgb, params, BATCH, PARAMS_DIM, LOW, nullptr, nullptr);

    // per-sample tiny MLP -> g (8192 x 128)
    tiny_mlp_kernel<<<BATCH / 8, 256>>>(f_low, params, g);

    // out = g @ wf2^T + bf2 + f + pf (8192 x 1024, K=128)
    sgemm_bias_kernel<<<dim3(F_DIM / BN, BATCH / BM), blk>>>(
        g, wf2, bf2, out, BATCH, F_DIM, LOW, f, pf);
}